// round 5
// baseline (speedup 1.0000x reference)
#include <cuda_runtime.h>

// MultiScaleProcessor: input [64,256,256,3] f32 -> output [64,4,256,256,3] f32
// scales = {32,64,128,256}; bilinear (linspace endpoints), zero-pad to 256.
//
// Compute blocks (4 rows): stage 8 source rows in static shared via coalesced
// float4 loads, bilinear from LDS, flush float4. Zero/copy blocks (8 rows):
// pure vectorized stores. Static smem only (36 KB) -> no cudaFuncSetAttribute.

#define HH 256
#define WW 256
#define NB 64
#define ROWF (WW * 3)             // 768 floats per row
#define NT 256

// zero/copy chunks: 8 rows
#define CHUNK 8
#define VPT (CHUNK * ROWF / 4 / NT)   // 6 float4 per thread

// compute chunks: 4 rows
#define CCHUNK 4
#define CVPT (CCHUNK * ROWF / 4 / NT) // 3 float4 per thread
#define PPT (CCHUNK * WW / NT)        // 4 pixels per thread
#define SRC_SLOTS (2 * CCHUNK)        // 8 slots (y0,y1 per output row)
#define LPT (SRC_SLOTS * ROWF / 4 / NT) // 6 float4 loads per thread

#define N_COMP_PER_B 56           // 8 (s=32) + 16 (s=64) + 32 (s=128), 4-row
#define N_COPY_PER_B 32           // s=256, 8-row
#define N_ZERO_PER_B 68           // 8-row
#define N_COMP (NB * N_COMP_PER_B)   // 3584
#define N_COPY (NB * N_COPY_PER_B)   // 2048
#define N_ZERO (NB * N_ZERO_PER_B)   // 4352

__global__ __launch_bounds__(NT) void msp_kernel(const float* __restrict__ in,
                                                 float* __restrict__ out) {
    __shared__ __align__(16) float srcrows[SRC_SLOTS * ROWF]; // 24 KB
    __shared__ __align__(16) float orows[CCHUNK * ROWF];      // 12 KB

    const int bid = blockIdx.x;
    const int tid = threadIdx.x;

    int b, sc, c4;  // batch, scale idx, 4-row chunk index (compute path)

    if (bid < N_COMP) {
        // ---- compute chunks (scheduled first: stragglers) ----
        b = bid / N_COMP_PER_B;
        const int k = bid % N_COMP_PER_B;
        if (k < 8)       { sc = 0; c4 = 28 + k; }        // s=32,  rows 112..143
        else if (k < 24) { sc = 1; c4 = 24 + (k - 8); }  // s=64,  rows 96..159
        else             { sc = 2; c4 = 16 + (k - 24); } // s=128, rows 64..191
    } else if (bid < N_COMP + N_COPY) {
        // ---- copy chunks (s=256), 8 rows ----
        const int i = bid - N_COMP;
        b = i / N_COPY_PER_B;
        const int yc = (i % N_COPY_PER_B) * CHUNK;
        float4* __restrict__ ochunk =
            (float4*)(out + ((((size_t)b * 4 + 3) * HH + yc) * ROWF));
        const float4* __restrict__ ichunk =
            (const float4*)(in + ((size_t)b * HH + yc) * ROWF);
#pragma unroll
        for (int j = 0; j < VPT; j++)
            __stcs(&ochunk[tid + j * NT], __ldg(&ichunk[tid + j * NT]));
        return;
    } else {
        // ---- zero chunks (pure store BW, fill the tail), 8 rows ----
        const int i = bid - N_COMP - N_COPY;
        b = i / N_ZERO_PER_B;
        const int k = i % N_ZERO_PER_B;
        int cy;
        if (k < 14)      { sc = 0; cy = k; }
        else if (k < 28) { sc = 0; cy = (k - 14) + 18; }
        else if (k < 40) { sc = 1; cy = (k - 28); }
        else if (k < 52) { sc = 1; cy = (k - 40) + 20; }
        else if (k < 60) { sc = 2; cy = (k - 52); }
        else             { sc = 2; cy = (k - 60) + 24; }
        const int yc = cy * CHUNK;
        float4* __restrict__ ochunk =
            (float4*)(out + ((((size_t)b * 4 + sc) * HH + yc) * ROWF));
        const float4 z = make_float4(0.f, 0.f, 0.f, 0.f);
#pragma unroll
        for (int j = 0; j < VPT; j++)
            __stcs(&ochunk[tid + j * NT], z);
        return;
    }

    // ---------------- compute path (4 output rows) ----------------
    const int s  = 32 << sc;
    const int p  = (256 - s) >> 1;
    const int yc = c4 * CCHUNK;
    const float inv = 255.0f / (float)(s - 1);
    const float* __restrict__ base = in + (size_t)b * (HH * ROWF);

    // Phase 1: stage 8 source rows (y0,y1 per output row), coalesced float4.
    {
        float4* __restrict__ s4 = (float4*)srcrows;
        const float4* __restrict__ i4 = (const float4*)base;
#pragma unroll
        for (int j = 0; j < LPT; j++) {
            const int v    = tid + j * NT;       // 0..1535
            const int slot = v / 192;            // 0..7
            const int col  = v - slot * 192;     // 0..191
            const int r    = slot >> 1;          // local output row 0..3
            const float fy = (float)(yc + r - p) * inv;
            const int  y0  = (int)fy;            // fy >= 0: trunc == floor
            const int  ysrc = (slot & 1) ? min(y0 + 1, HH - 1) : y0;
            s4[v] = __ldg(&i4[ysrc * (ROWF / 4) + col]);
        }
    }
    __syncthreads();

    // Phase 2: bilinear from shared into output staging.
#pragma unroll
    for (int j = 0; j < PPT; j++) {
        const int pi = tid + j * NT;   // 0..1023
        const int r  = pi >> 8;        // local row 0..3
        const int x  = pi & 255;       // column 0..255
        float* dst = &orows[r * ROWF + 3 * x];
        if (x < p || x >= p + s) {
            dst[0] = 0.f; dst[1] = 0.f; dst[2] = 0.f;
        } else {
            const float fy = (float)(yc + r - p) * inv;
            const int   y0 = (int)fy;
            const float wy = fy - (float)y0;

            const float fx = (float)(x - p) * inv;
            const int   x0 = (int)fx;
            const int   x1 = min(x0 + 1, WW - 1);
            const float wx = fx - (float)x0;

            const float* __restrict__ r0 = &srcrows[(2 * r)     * ROWF];
            const float* __restrict__ r1 = &srcrows[(2 * r + 1) * ROWF];
            const float wx0 = 1.f - wx;
            const float wy0 = 1.f - wy;
#pragma unroll
            for (int c = 0; c < 3; c++) {
                const float t  = r0[3 * x0 + c] * wx0 + r0[3 * x1 + c] * wx;
                const float bt = r1[3 * x0 + c] * wx0 + r1[3 * x1 + c] * wx;
                dst[c] = t * wy0 + bt * wy;
            }
        }
    }
    __syncthreads();

    // Phase 3: flush 4 rows, float4.
    float4* __restrict__ ochunk =
        (float4*)(out + ((((size_t)b * 4 + sc) * HH + yc) * ROWF));
    const float4* __restrict__ srow = (const float4*)orows;
#pragma unroll
    for (int j = 0; j < CVPT; j++)
        __stcs(&ochunk[tid + j * NT], srow[tid + j * NT]);
}

extern "C" void kernel_launch(void* const* d_in, const int* in_sizes, int n_in,
                              void* d_out, int out_size) {
    const float* in  = (const float*)d_in[0];
    float*       out = (float*)d_out;
    (void)in_sizes; (void)n_in; (void)out_size;

    msp_kernel<<<N_COMP + N_COPY + N_ZERO, NT>>>(in, out);
}

// round 8
// speedup vs baseline: 1.1304x; 1.1304x over previous
#include <cuda_runtime.h>
#include <cstdint>

// MultiScaleProcessor: input [64,256,256,3] f32 -> output [64,4,256,256,3] f32
// scales = {32,64,128,256}; bilinear (linspace endpoints), zero-pad to 256.
//
// Experiment: ALL output stores go through the TMA bulk-store path
// (cp.async.bulk.global.shared::cta) instead of per-thread STG.128, to test
// whether the flat ~4.4 TB/s across five STG-based variants is an SM-store-
// path limit or the DRAM write ceiling.

#define HH 256
#define WW 256
#define NB 64
#define ROWF (WW * 3)            // 768 floats per row
#define CHUNK 8                  // rows per block; pads (112,96,64) %8==0
#define NT 256
#define CBYTES (CHUNK * ROWF * 4)    // 24576 bytes per chunk
#define CROWV (CHUNK * ROWF / 4)     // 1536 float4 per chunk
#define VPT (CROWV / NT)             // 6 float4 per thread
#define PPT (CHUNK * WW / NT)        // 8 pixels per thread

__device__ __forceinline__ uint32_t smem_u32(const void* p) {
    uint32_t a;
    asm("{ .reg .u64 t; cvta.to.shared.u64 t, %1; cvt.u32.u64 %0, t; }"
        : "=r"(a) : "l"(p));
    return a;
}

__device__ __forceinline__ void bulk_store_flush(void* gdst, uint32_t ssrc,
                                                 uint32_t bytes) {
    asm volatile("fence.proxy.async.shared::cta;" ::: "memory");
    asm volatile(
        "cp.async.bulk.global.shared::cta.bulk_group [%0], [%1], %2;"
        :: "l"(gdst), "r"(ssrc), "r"(bytes) : "memory");
    asm volatile("cp.async.bulk.commit_group;" ::: "memory");
    asm volatile("cp.async.bulk.wait_group 0;" ::: "memory");
}

__global__ __launch_bounds__(NT) void msp_kernel(const float* __restrict__ in,
                                                 float* __restrict__ out) {
    __shared__ __align__(16) float rows[CHUNK * ROWF];  // 24 KB staging

    const int yc  = blockIdx.x * CHUNK;  // first output row of this chunk
    const int sc  = blockIdx.y;          // scale index
    const int b   = blockIdx.z;          // batch
    const int s   = 32 << sc;
    const int p   = (256 - s) >> 1;
    const int tid = threadIdx.x;

    float* const gdst = out + ((((size_t)b * 4 + sc) * HH + yc) * ROWF);
    float4* const s4  = (float4*)rows;

    if (s == 256) {
        // native: LDG.128 -> STS.128 stage, then one 24KB bulk store
        const float4* __restrict__ ichunk =
            (const float4*)(in + ((size_t)b * HH + yc) * ROWF);
#pragma unroll
        for (int j = 0; j < VPT; j++)
            s4[tid + j * NT] = __ldg(&ichunk[tid + j * NT]);
    } else if (yc + CHUNK <= p || yc >= p + s) {
        // fully padded chunk: zero the staging buffer
        const float4 z = make_float4(0.f, 0.f, 0.f, 0.f);
#pragma unroll
        for (int j = 0; j < VPT; j++)
            s4[tid + j * NT] = z;
    } else {
        // compute chunk: bilinear into shared
        const float inv = 255.0f / (float)(s - 1);
        const float* __restrict__ base = in + (size_t)b * (HH * ROWF);
#pragma unroll
        for (int j = 0; j < PPT; j++) {
            const int pi = tid + j * NT;   // 0..2047
            const int r  = pi >> 8;        // local row 0..7
            const int x  = pi & 255;       // column 0..255
            float* dst = &rows[r * ROWF + 3 * x];
            if (x < p || x >= p + s) {
                dst[0] = 0.f; dst[1] = 0.f; dst[2] = 0.f;
            } else {
                const int   y  = yc + r - p;
                const float fy = (float)y * inv;
                const int   y0 = (int)fy;          // fy >= 0: trunc == floor
                const int   y1 = min(y0 + 1, HH - 1);
                const float wy = fy - (float)y0;

                const float fx = (float)(x - p) * inv;
                const int   x0 = (int)fx;
                const int   x1 = min(x0 + 1, WW - 1);
                const float wx = fx - (float)x0;

                const float* __restrict__ r0 = base + (size_t)y0 * ROWF;
                const float* __restrict__ r1 = base + (size_t)y1 * ROWF;
                const float wx0 = 1.f - wx;
                const float wy0 = 1.f - wy;
#pragma unroll
                for (int c = 0; c < 3; c++) {
                    const float t  = __ldg(r0 + 3 * x0 + c) * wx0 +
                                     __ldg(r0 + 3 * x1 + c) * wx;
                    const float bt = __ldg(r1 + 3 * x0 + c) * wx0 +
                                     __ldg(r1 + 3 * x1 + c) * wx;
                    dst[c] = t * wy0 + bt * wy;
                }
            }
        }
    }

    __syncthreads();
    if (tid == 0)
        bulk_store_flush(gdst, smem_u32(rows), CBYTES);
}

extern "C" void kernel_launch(void* const* d_in, const int* in_sizes, int n_in,
                              void* d_out, int out_size) {
    const float* in  = (const float*)d_in[0];
    float*       out = (float*)d_out;
    (void)in_sizes; (void)n_in; (void)out_size;

    dim3 grid(HH / CHUNK, 4, NB);  // 32 x 4 x 64 = 8192 blocks
    msp_kernel<<<grid, NT>>>(in, out);
}